// round 6
// baseline (speedup 1.0000x reference)
#include <cuda_runtime.h>
#include <math.h>
#include <stdint.h>

// ---------------------------------------------------------------------------
// Problem constants
// ---------------------------------------------------------------------------
#define N_TOK 4096
#define DIM   2048
#define ODIM  2048
#define NE    8

// GEMM tiling (swapped orientation: M-axis = output-n, N-axis = tokens)
#define BMN  128               // output-n per CTA tile
#define BTOK 256               // tokens per CTA tile
#define BK   32
#define STAGES 3
#define KT_TOTAL (DIM / BK)    // 64

#define NTILES_Y (N_TOK / BTOK)       // 16 (worst case)
#define NTILES_X (ODIM / BMN)         // 16
#define NTILES   (NE * NTILES_Y * NTILES_X)   // 2048
#define GRID_CTAS 148

// SMEM layout (byte offsets)
#define OFF_TS   0                    // 256 ints
#define OFF_WS   1024                 // 256 floats
#define OFF_TILE 2048                 // 1 int (tile broadcast)
#define OFF_A    3072
#define A_STG    16384                // 128 rows x 128B
#define OFF_B    (OFF_A + STAGES * A_STG)     // 52224
#define B_STG    32768                // 256 rows x 128B
#define SMEM_TOTAL (OFF_B + STAGES * B_STG)   // 150528
#define OFF_C    OFF_A                // epilogue Csm overlays stage buffers
#define C_PAD    132                  // Csm row stride (floats)

// ---------------------------------------------------------------------------
// Device scratch (allocation-free)
// ---------------------------------------------------------------------------
__device__ float g_xq [(size_t)N_TOK * DIM];              // tf32-rounded x
__device__ float g_WeT[(size_t)NE * ODIM * DIM];          // tf32-rounded We^T: [e][n][k]
__device__ float g_partial[(size_t)N_TOK * 2 * ODIM];
__device__ int   g_count[NE];
__device__ int   g_slot[NE][N_TOK];                       // token*2 + rank
__device__ float g_w[NE][N_TOK];
__device__ int   g_tile_ctr;

// ---------------------------------------------------------------------------
// PTX helpers (base sm_100 target — no 'a' features)
// ---------------------------------------------------------------------------
__device__ __forceinline__ uint32_t smem_u32(const void* p) {
    uint32_t a;
    asm("{ .reg .u64 t; cvta.to.shared.u64 t, %1; cvt.u32.u64 %0, t; }" : "=r"(a) : "l"(p));
    return a;
}
__device__ __forceinline__ float tf32_rna(float v) {
    uint32_t u;
    asm("cvt.rna.tf32.f32 %0, %1;" : "=r"(u) : "f"(v));
    return __uint_as_float(u);
}
__device__ __forceinline__ void cp_async16(uint32_t smem_addr, const void* gmem) {
    asm volatile("cp.async.cg.shared.global [%0], [%1], 16;" :: "r"(smem_addr), "l"(gmem));
}
__device__ __forceinline__ void cp_commit() { asm volatile("cp.async.commit_group;"); }
template <int N>
__device__ __forceinline__ void cp_wait() { asm volatile("cp.async.wait_group %0;" :: "n"(N)); }

__device__ __forceinline__ void ldmatrix_x4(uint32_t r[4], uint32_t addr) {
    asm volatile("ldmatrix.sync.aligned.m8n8.x4.shared.b16 {%0,%1,%2,%3}, [%4];"
                 : "=r"(r[0]), "=r"(r[1]), "=r"(r[2]), "=r"(r[3]) : "r"(addr));
}
__device__ __forceinline__ void mma_tf32(float c[4], const uint32_t a[4],
                                         uint32_t b0, uint32_t b1) {
    asm volatile(
        "mma.sync.aligned.m16n8k8.row.col.f32.tf32.tf32.f32 "
        "{%0,%1,%2,%3}, {%4,%5,%6,%7}, {%8,%9}, {%0,%1,%2,%3};"
        : "+f"(c[0]), "+f"(c[1]), "+f"(c[2]), "+f"(c[3])
        : "r"(a[0]), "r"(a[1]), "r"(a[2]), "r"(a[3]), "r"(b0), "r"(b1));
}

// ---------------------------------------------------------------------------
// Kernel 1a/1b: round x to tf32 (rna) into g_xq; reset counters
// ---------------------------------------------------------------------------
__global__ void conv_x_kernel(const float4* __restrict__ x, int base) {
    int i = base + blockIdx.x * blockDim.x + threadIdx.x;  // float4 index
    float4 v = x[i];
    v.x = tf32_rna(v.x); v.y = tf32_rna(v.y); v.z = tf32_rna(v.z); v.w = tf32_rna(v.w);
    ((float4*)g_xq)[i] = v;
    if (base == 0) {
        if (i < NE) g_count[i] = 0;
        if (i == 0) g_tile_ctr = 0;
    }
}

// ---------------------------------------------------------------------------
// Kernel 2a/2b: WeT[e][n][k] = rna(We[e][k][n])  (32x32 tiled transpose)
// ---------------------------------------------------------------------------
__global__ void convT_kernel(const float* __restrict__ We, int e_base) {
    __shared__ float t[32][33];
    int e  = e_base + blockIdx.z;
    int d0 = blockIdx.y * 32;
    int o0 = blockIdx.x * 32;
    int tx = threadIdx.x, ty = threadIdx.y;            // (32, 8)

    const float* src = We + ((size_t)e * DIM + d0) * ODIM + o0;
#pragma unroll
    for (int i = 0; i < 4; i++)
        t[ty + i * 8][tx] = src[(size_t)(ty + i * 8) * ODIM + tx];
    __syncthreads();
    float* dst = g_WeT + ((size_t)e * ODIM + o0) * DIM + d0;
#pragma unroll
    for (int i = 0; i < 4; i++)
        dst[(size_t)(ty + i * 8) * DIM + tx] = tf32_rna(t[tx][ty + i * 8]);
}

// ---------------------------------------------------------------------------
// Kernel 3: gating + top-2 routing (one warp per token)
// ---------------------------------------------------------------------------
__global__ void gating_kernel(const float* __restrict__ x,
                              const float* __restrict__ Wg,
                              const float* __restrict__ bg) {
    int warp = (blockIdx.x * blockDim.x + threadIdx.x) >> 5;
    int lane = threadIdx.x & 31;
    if (warp >= N_TOK) return;

    const float* xr = x + (size_t)warp * DIM;
    float acc[NE];
#pragma unroll
    for (int e = 0; e < NE; e++) acc[e] = 0.f;
    for (int k = lane; k < DIM; k += 32) {
        float xv = xr[k];
        const float* wr = Wg + (size_t)k * NE;
#pragma unroll
        for (int e = 0; e < NE; e++) acc[e] = fmaf(xv, wr[e], acc[e]);
    }
#pragma unroll
    for (int e = 0; e < NE; e++) {
#pragma unroll
        for (int off = 16; off > 0; off >>= 1)
            acc[e] += __shfl_xor_sync(0xFFFFFFFFu, acc[e], off);
    }
    if (lane == 0) {
        float v[NE];
#pragma unroll
        for (int e = 0; e < NE; e++) v[e] = acc[e] + bg[e];
        int i0 = 0;
#pragma unroll
        for (int e = 1; e < NE; e++) if (v[e] > v[i0]) i0 = e;
        int i1 = (i0 == 0) ? 1 : 0;
#pragma unroll
        for (int e = 0; e < NE; e++) if (e != i0 && v[e] > v[i1]) i1 = e;

        float t  = expf(v[i1] - v[i0]);
        float w0 = 1.0f / (1.0f + t);
        float w1 = 1.0f - w0;

        int p0 = atomicAdd(&g_count[i0], 1);
        g_slot[i0][p0] = warp * 2 + 0;  g_w[i0][p0] = w0;
        int p1 = atomicAdd(&g_count[i1], 1);
        g_slot[i1][p1] = warp * 2 + 1;  g_w[i1][p1] = w1;
    }
}

// ---------------------------------------------------------------------------
// Kernel 4: persistent tf32 mma.sync gather-GEMM (swapped orientation).
//   D[n, tok] = sum_k WeT[e, n0+n, k] * xq[tok, k]
//   partial[slot(tok), n0+n] = w(tok) * (D + be[e, n0+n])
// 148 persistent CTAs, dynamic tile counter. CTA tile 128n x 256tok,
// 8 warps (2n x 4tok), warp tile 64x64. 3-stage cp.async; ldmatrix.x4 both
// operands; explicit fragment double-buffer across kk. occ 1 (255 regs).
// ---------------------------------------------------------------------------
__global__ void __launch_bounds__(256)
moe_mma_kernel(const float* __restrict__ be) {
    extern __shared__ char smem[];
    const uint32_t sb = smem_u32(smem);
    const int tid  = threadIdx.x;
    const int wid  = tid >> 5;
    const int lane = tid & 31;

    int*   ts_s = (int*)(smem + OFF_TS);
    float* ws_s = (float*)(smem + OFF_WS);
    int*   tile_s = (int*)(smem + OFF_TILE);

    const int wm = wid & 1;             // n-block (64 rows)
    const int wt = wid >> 1;            // tok-block (64 cols)

    // ldmatrix per-lane address components (same mapping validated in R5)
    const uint32_t xorv  = (uint32_t)((lane & 7) << 4);
    const int aRowL      = (lane & 7) + ((lane & 8) ? 8 : 0);
    const uint32_t aBsel = (lane & 16) ? 16u : 0u;
    const int bRowL      = (lane & 7) + ((lane & 16) ? 8 : 0);
    const uint32_t bBsel = (lane & 8) ? 16u : 0u;
    const uint32_t aBaseL = sb + OFF_A + (uint32_t)((wm * 64 + aRowL) * 128);
    const uint32_t bBaseL = sb + OFF_B + (uint32_t)((wt * 64 + bRowL) * 128);
    const int g  = lane >> 2;
    const int t4 = lane & 3;

    while (true) {
        __syncthreads();                               // smem + tile_s reuse fence
        if (tid == 0) *tile_s = atomicAdd(&g_tile_ctr, 1);
        __syncthreads();
        const int tile = *tile_s;
        if (tile >= NTILES) break;

        const int e  = tile >> 8;
        const int ty = (tile >> 4) & 15;
        const int nx = tile & 15;
        const int count = g_count[e];
        const int t0    = ty * BTOK;
        if (t0 >= count) continue;
        const int n0    = nx * BMN;

        const int mi0 = t0 + tid;
        if (mi0 < count) { ts_s[tid] = g_slot[e][mi0]; ws_s[tid] = g_w[e][mi0]; }
        else             { ts_s[tid] = 0;              ws_s[tid] = 0.f;         }
        __syncthreads();

        const float* WeP = g_WeT + (size_t)e * ODIM * DIM;

        // ---- cp.async precompute (32-bit element offsets) ----
        uint32_t aoff[4], adst[4];
#pragma unroll
        for (int j = 0; j < 4; j++) {
            int c = tid + 256 * j;                     // A: 1024 chunks/stage
            int row = c >> 3, col = c & 7;
            aoff[j] = (uint32_t)((n0 + row) * DIM + col * 4);
            adst[j] = sb + OFF_A + (uint32_t)(row * 128 + ((col * 16) ^ ((row & 7) << 4)));
        }
        uint32_t boff[8], bdst[8];
#pragma unroll
        for (int j = 0; j < 8; j++) {
            int c = tid + 256 * j;                     // B: 2048 chunks/stage
            int row = c >> 3, col = c & 7;
            boff[j] = (uint32_t)((ts_s[row] >> 1) * DIM + col * 4);
            bdst[j] = sb + OFF_B + (uint32_t)(row * 128 + ((col * 16) ^ ((row & 7) << 4)));
        }

        // ---- prologue: stages 0..1 ----
#pragma unroll
        for (int kt = 0; kt < STAGES - 1; kt++) {
#pragma unroll
            for (int j = 0; j < 4; j++) cp_async16(adst[j] + kt * A_STG, WeP + aoff[j] + kt * BK);
#pragma unroll
            for (int j = 0; j < 8; j++) cp_async16(bdst[j] + kt * B_STG, g_xq + boff[j] + kt * BK);
            cp_commit();
        }

        float acc[4][8][4];
#pragma unroll
        for (int mi = 0; mi < 4; mi++)
#pragma unroll
            for (int ni = 0; ni < 8; ni++)
#pragma unroll
                for (int r = 0; r < 4; r++) acc[mi][ni][r] = 0.f;

        int sCur = 0, sIn = STAGES - 1;
        for (int kt = 0; kt < KT_TOTAL; ++kt) {
            cp_wait<STAGES - 2>();
            __syncthreads();

            if (kt + STAGES - 1 < KT_TOTAL) {
                const int kn = kt + STAGES - 1;
#pragma unroll
                for (int j = 0; j < 4; j++) cp_async16(adst[j] + sIn * A_STG, WeP + aoff[j] + kn * BK);
#pragma unroll
                for (int j = 0; j < 8; j++) cp_async16(bdst[j] + sIn * B_STG, g_xq + boff[j] + kn * BK);
                cp_commit();
                if (++sIn == STAGES) sIn = 0;
            } else {
                cp_commit();
            }

            const uint32_t aSt = aBaseL + sCur * A_STG;
            const uint32_t bSt = bBaseL + sCur * B_STG;

            // fragment double-buffer across kk
            uint32_t af[2][4][4], bf[2][4][4];
#pragma unroll
            for (int mi = 0; mi < 4; mi++)
                ldmatrix_x4(af[0][mi], aSt + mi * 2048 + (aBsel ^ xorv));
#pragma unroll
            for (int j = 0; j < 4; j++)
                ldmatrix_x4(bf[0][j], bSt + j * 2048 + (bBsel ^ xorv));

#pragma unroll
            for (int kk = 0; kk < 4; kk++) {
                const int cur = kk & 1, nxt = cur ^ 1;
                if (kk < 3) {
                    const uint32_t aI = ((uint32_t)((kk + 1) * 32) + aBsel) ^ xorv;
                    const uint32_t bI = ((uint32_t)((kk + 1) * 32) + bBsel) ^ xorv;
#pragma unroll
                    for (int mi = 0; mi < 4; mi++)
                        ldmatrix_x4(af[nxt][mi], aSt + mi * 2048 + aI);
#pragma unroll
                    for (int j = 0; j < 4; j++)
                        ldmatrix_x4(bf[nxt][j], bSt + j * 2048 + bI);
                }
#pragma unroll
                for (int mi = 0; mi < 4; mi++)
#pragma unroll
                    for (int j = 0; j < 4; j++) {
                        mma_tf32(acc[mi][j * 2 + 0], af[cur][mi], bf[cur][j][0], bf[cur][j][1]);
                        mma_tf32(acc[mi][j * 2 + 1], af[cur][mi], bf[cur][j][2], bf[cur][j][3]);
                    }
            }
            if (++sCur == STAGES) sCur = 0;
        }

        // ---- epilogue: transpose D[n][tok] -> Csm[tok][n], scale, store ----
        cp_wait<0>();
        __syncthreads();
        float* Csm = (float*)(smem + OFF_C);
#pragma unroll
        for (int mi = 0; mi < 4; mi++) {
#pragma unroll
            for (int ni = 0; ni < 8; ni++) {
                const int n   = wm * 64 + mi * 16 + g;
                const int tok = wt * 64 + ni * 8 + 2 * t4;
                Csm[(size_t)tok       * C_PAD + n]     = acc[mi][ni][0];
                Csm[(size_t)(tok + 1) * C_PAD + n]     = acc[mi][ni][1];
                Csm[(size_t)tok       * C_PAD + n + 8] = acc[mi][ni][2];
                Csm[(size_t)(tok + 1) * C_PAD + n + 8] = acc[mi][ni][3];
            }
        }
        __syncthreads();

        if (t0 + tid < count) {
            const int   slot = ts_s[tid];
            const float wv   = ws_s[tid];
            float*       dst = g_partial + (size_t)slot * ODIM + n0;
            const float* bep = be + (size_t)e * ODIM + n0;
            const float* crow = Csm + (size_t)tid * C_PAD;
#pragma unroll
            for (int i = 0; i < 32; i++) {
                float4 c  = *(const float4*)(crow + i * 4);
                float4 bv = *(const float4*)(bep + i * 4);
                float4 o;
                o.x = wv * (c.x + bv.x);
                o.y = wv * (c.y + bv.y);
                o.z = wv * (c.z + bv.z);
                o.w = wv * (c.w + bv.w);
                *(float4*)(dst + i * 4) = o;
            }
        }
    }
}

// ---------------------------------------------------------------------------
// Kernel 5: out[t, n] = partial[2t, n] + partial[2t+1, n]
// ---------------------------------------------------------------------------
__global__ void combine_kernel(float4* __restrict__ out) {
    int i  = blockIdx.x * blockDim.x + threadIdx.x;     // exactly N*O/4
    int t  = i >> 9;
    int n4 = i & 511;
    const float4* p0 = (const float4*)(g_partial + (size_t)(t * 2)     * ODIM) + n4;
    const float4* p1 = (const float4*)(g_partial + (size_t)(t * 2 + 1) * ODIM) + n4;
    float4 a = *p0, b = *p1;
    out[i] = make_float4(a.x + b.x, a.y + b.y, a.z + b.z, a.w + b.w);
}

// ---------------------------------------------------------------------------
// Launch — GEMM is launch index 5, where ncu (-s 5 -c 1) captures.
// ---------------------------------------------------------------------------
extern "C" void kernel_launch(void* const* d_in, const int* in_sizes, int n_in,
                              void* d_out, int out_size) {
    const float* x  = (const float*)d_in[0];
    const float* Wg = (const float*)d_in[1];
    const float* bg = (const float*)d_in[2];
    const float* We = (const float*)d_in[3];
    const float* be = (const float*)d_in[4];
    float* out = (float*)d_out;

    static int smem_set = 0;
    if (!smem_set) {
        cudaFuncSetAttribute(moe_mma_kernel, cudaFuncAttributeMaxDynamicSharedMemorySize, SMEM_TOTAL);
        smem_set = 1;
    }

    const int xq4_half = (N_TOK * DIM / 4) / 2;

    // 0,1) tf32-round x in two halves (+ reset counters/tile ctr in half 0)
    conv_x_kernel<<<xq4_half / 256, 256>>>((const float4*)x, 0);
    conv_x_kernel<<<xq4_half / 256, 256>>>((const float4*)x, xq4_half);

    // 2,3) tf32-round + transpose We -> WeT[e][n][k], two expert halves
    dim3 tgrid(ODIM / 32, DIM / 32, NE / 2);
    convT_kernel<<<tgrid, dim3(32, 8)>>>(We, 0);
    convT_kernel<<<tgrid, dim3(32, 8)>>>(We, NE / 2);

    // 4) gating + top-2 routing
    gating_kernel<<<(N_TOK * 32) / 256, 256>>>(x, Wg, bg);

    // 5) persistent tf32 mma.sync gather-GEMM (captured by ncu)
    moe_mma_kernel<<<GRID_CTAS, 256, SMEM_TOTAL>>>(be);

    // 6) combine
    combine_kernel<<<(N_TOK * ODIM / 4) / 256, 256>>>((float4*)out);
}